// round 1
// baseline (speedup 1.0000x reference)
#include <cuda_runtime.h>
#include <cuda_bf16.h>
#include <cstdint>

// Problem constants
#define T_   1024
#define BZ   4
#define E_   1024
#define NH   16
#define HD   64
#define BH   64          // bsz * nh
#define SLEN 1025        // src_len = T + 1 (bias_kv)
#define M_   4096        // T*B rows of the projection GEMMs
#define QSCALE 0.00390625f   // hd^-0.5 / ALPHA = (1/8)/32 = 1/256

// ---------------- scratch (device globals; no allocation allowed) ----------
__device__ float g_Q[(size_t)BH * T_ * HD];        // [x][y][d]
__device__ float g_K[(size_t)BH * SLEN * HD];      // [x][yk][d]
__device__ float g_V[(size_t)BH * SLEN * HD];      // [x][yk][d]
__device__ float g_gate[(size_t)BH * T_];          // [x][y]
__device__ float g_pb[(size_t)NH * 2048];          // [h][rel+1023]
__device__ float g_attn[(size_t)M_ * E_];          // (y*4+b, (x%16)*64+d)

// ---------------- tiled SGEMM: 128x128x16, 256 thr, 8x8 per thread ---------
// MODE 0: Q proj (scale + scrambled scatter)
// MODE 1: K proj, MODE 2: V proj (scrambled scatter, rows 0..1023)
// MODE 3: output proj (A = g_attn, C = d_out)
template<int MODE>
__global__ __launch_bounds__(256)
void sgemm_kernel(const float* __restrict__ A,
                  const float* __restrict__ Bw,
                  const float* __restrict__ bias,
                  float* __restrict__ Cout)
{
    const int K = 1024, N = 1024;
    __shared__ float As[16][132];   // transposed A tile [k][m], padded
    __shared__ float Bs[16][128];   // [k][n]

    const float* Ap = (MODE == 3) ? (const float*)g_attn : A;

    int tid = threadIdx.x;
    int bm = blockIdx.y, bn = blockIdx.x;
    int tr = tid >> 4, tc = tid & 15;

    float acc[8][8] = {};

    const int arow = tid >> 2;            // 0..63
    const int akf4 = (tid & 3) * 4;       // k offset 0,4,8,12
    const int brow = tid >> 5;            // 0..7
    const int bcol = (tid & 31) * 4;      // 0..124

    for (int k0 = 0; k0 < K; k0 += 16) {
        #pragma unroll
        for (int half = 0; half < 2; half++) {
            int r = arow + half * 64;
            float4 a = *reinterpret_cast<const float4*>(
                &Ap[(size_t)(bm * 128 + r) * K + k0 + akf4]);
            As[akf4 + 0][r] = a.x; As[akf4 + 1][r] = a.y;
            As[akf4 + 2][r] = a.z; As[akf4 + 3][r] = a.w;
        }
        #pragma unroll
        for (int half = 0; half < 2; half++) {
            int kk = brow + half * 8;
            float4 b = *reinterpret_cast<const float4*>(
                &Bw[(size_t)(k0 + kk) * N + bn * 128 + bcol]);
            *reinterpret_cast<float4*>(&Bs[kk][bcol]) = b;
        }
        __syncthreads();
        #pragma unroll
        for (int k = 0; k < 16; k++) {
            float ar[8], br[8];
            *(float4*)&ar[0] = *(float4*)&As[k][tr * 8];
            *(float4*)&ar[4] = *(float4*)&As[k][tr * 8 + 4];
            *(float4*)&br[0] = *(float4*)&Bs[k][tc * 8];
            *(float4*)&br[4] = *(float4*)&Bs[k][tc * 8 + 4];
            #pragma unroll
            for (int i = 0; i < 8; i++)
                #pragma unroll
                for (int j = 0; j < 8; j++)
                    acc[i][j] += ar[i] * br[j];
        }
        __syncthreads();
    }

    #pragma unroll
    for (int i = 0; i < 8; i++) {
        int m = bm * 128 + tr * 8 + i;
        #pragma unroll
        for (int j = 0; j < 8; j++) {
            int n = bn * 128 + tc * 8 + j;
            float v = acc[i][j] + bias[n];
            if (MODE == 3) {
                Cout[(size_t)m * E_ + n] = v;
            } else {
                int t = m >> 2, b = m & 3;      // m = t*4 + b
                int h = n >> 6, d = n & 63;     // n = h*64 + d
                if (MODE == 0) {
                    // scrambled reshape: x = b*16 + t/64 ; y = (t%64)*16 + h
                    int x = b * 16 + (t >> 6);
                    int y = ((t & 63) << 4) | h;
                    g_Q[((size_t)x * T_ + y) * HD + d] = v * QSCALE;
                } else {
                    // u = s*16 + h ; x = b*16 + u/1025 ; y = u%1025
                    int u = t * 16 + h;         // here m-row index is s
                    int x = b * 16 + u / 1025;
                    int y = u % 1025;
                    if (MODE == 1)
                        g_K[((size_t)x * SLEN + y) * HD + d] = v;
                    else
                        g_V[((size_t)x * SLEN + y) * HD + d] = v;
                }
            }
        }
    }
}

// ---------------- bias_kv row: s=1024 -> u=16384+h -> x=b*16+15, y=1009+h ---
__global__ void biaskv_kernel(const float* __restrict__ bias_k,
                              const float* __restrict__ bias_v)
{
    int i = blockIdx.x * blockDim.x + threadIdx.x;   // 4*16*64 = 4096
    if (i >= BZ * NH * HD) return;
    int b = i >> 10, h = (i >> 6) & 15, d = i & 63;
    int x = b * 16 + 15;
    int y = 1009 + h;
    g_K[((size_t)x * SLEN + y) * HD + d] = bias_k[h * HD + d];
    g_V[((size_t)x * SLEN + y) * HD + d] = bias_v[h * HD + d];
}

// ---------------- relative position bias table: depends only on (s-t) ------
__global__ void pb_kernel(const float* __restrict__ rel_emb)
{
    int d = blockIdx.x * blockDim.x + threadIdx.x;   // 0..2047
    if (d >= 2048) return;
    int rel = d - 1023;
    int bkt = rel > 0 ? 16 : 0;
    int a = rel < 0 ? -rel : rel;
    int bu;
    if (a < 8) {
        bu = a;
    } else {
        float lf = logf((float)a * 0.125f + 1e-6f) * (8.0f / 2.772588722239781f);
        int large = 8 + (int)lf;
        bu = large < 15 ? large : 15;
    }
    int bucket = bkt + bu;
    #pragma unroll
    for (int h = 0; h < NH; h++)
        g_pb[h * 2048 + d] = rel_emb[bucket * NH + h];
}

// ---------------- gate: sigmoid((q_unscaled . sum_j grep_w[:,j]) + sum(b)) --
__global__ __launch_bounds__(256)
void gate_kernel(const float* __restrict__ grep_w,
                 const float* __restrict__ grep_b,
                 const float* __restrict__ grep_a)
{
    __shared__ float gws[64];
    __shared__ float gbs;
    int tid = threadIdx.x;
    if (tid < 64) {
        float s = 0.f;
        #pragma unroll
        for (int j = 0; j < 8; j++) s += grep_w[tid * 8 + j];
        gws[tid] = s;
    }
    if (tid == 64) {
        float s = 0.f;
        #pragma unroll
        for (int j = 0; j < 8; j++) s += grep_b[j];
        gbs = s;
    }
    __syncthreads();
    int warp = tid >> 5, lane = tid & 31;
    int row = blockIdx.x * 8 + warp;                 // row = x*1024 + y
    if (row < BH * T_) {
        const float* q = &g_Q[(size_t)row * HD];
        float s = q[lane] * gws[lane] + q[lane + 32] * gws[lane + 32];
        #pragma unroll
        for (int off = 16; off; off >>= 1)
            s += __shfl_xor_sync(0xffffffffu, s, off);
        if (lane == 0) {
            int hx = (row >> 10) & 15;               // x % 16
            float val = s * 256.0f + gbs;            // undo QSCALE
            float sig = 1.0f / (1.0f + __expf(-val));
            g_gate[row] = sig * grep_a[hx];
        }
    }
}

// ---------------- fused attention: 64 q-rows/block, 17 chunks of 64 keys ---
#define SATT 68
__global__ __launch_bounds__(256)
void attn_kernel()
{
    extern __shared__ float sm[];
    float* Qs   = sm;                    // [d][r] 64x68
    float* Ks   = Qs + 64 * SATT;        // [d][s]
    float* Vs   = Ks + 64 * SATT;        // [s][d]
    float* Ss   = Vs + 64 * SATT;        // [s][r]  (scores then probs)
    float* red  = Ss + 64 * SATT;        // [4][64]
    float* m_s  = red + 256;
    float* l_s  = m_s + 64;
    float* al_s = l_s + 64;
    float* gt_s = al_s + 64;

    int tid = threadIdx.x;
    int x   = blockIdx.y;                // scrambled batch-head
    int t0  = blockIdx.x * 64;           // y-row tile start
    int hx  = x & 15;                    // "head" for pb
    int bx  = x >> 4;                    // "batch" for output scatter

    // load Q tile transposed
    #pragma unroll
    for (int it = 0; it < 4; it++) {
        int q = tid + it * 256;
        int r = q >> 4;
        int dd = (q & 15) * 4;
        float4 v = *(const float4*)&g_Q[((size_t)x * T_ + t0 + r) * HD + dd];
        Qs[(dd + 0) * SATT + r] = v.x; Qs[(dd + 1) * SATT + r] = v.y;
        Qs[(dd + 2) * SATT + r] = v.z; Qs[(dd + 3) * SATT + r] = v.w;
    }
    if (tid < 64) {
        gt_s[tid] = g_gate[(size_t)x * T_ + t0 + tid];
        m_s[tid] = -1e30f;
        l_s[tid] = 0.f;
    }
    __syncthreads();

    int tr = tid >> 4, tc = tid & 15;
    int r0 = tr * 4, c0 = tc * 4;
    float o[4][4] = {};
    float gate_r[4];
    #pragma unroll
    for (int i = 0; i < 4; i++) gate_r[i] = gt_s[r0 + i];

    for (int ch = 0; ch < 17; ch++) {
        int s0 = ch * 64;
        // load K (transposed) and V chunk, zero-pad past SLEN
        #pragma unroll
        for (int it = 0; it < 4; it++) {
            int q = tid + it * 256;
            int s = q >> 4;
            int dd = (q & 15) * 4;
            int sg = s0 + s;
            float4 kv = make_float4(0.f, 0.f, 0.f, 0.f);
            float4 vv = make_float4(0.f, 0.f, 0.f, 0.f);
            if (sg < SLEN) {
                kv = *(const float4*)&g_K[((size_t)x * SLEN + sg) * HD + dd];
                vv = *(const float4*)&g_V[((size_t)x * SLEN + sg) * HD + dd];
            }
            Ks[(dd + 0) * SATT + s] = kv.x; Ks[(dd + 1) * SATT + s] = kv.y;
            Ks[(dd + 2) * SATT + s] = kv.z; Ks[(dd + 3) * SATT + s] = kv.w;
            *(float4*)&Vs[s * SATT + dd] = vv;
        }
        __syncthreads();

        // S = Q @ K^T (64x64), 4x4 per thread
        float sacc[4][4] = {};
        #pragma unroll
        for (int k = 0; k < 64; k++) {
            float a[4], bb[4];
            *(float4*)a  = *(float4*)&Qs[k * SATT + r0];
            *(float4*)bb = *(float4*)&Ks[k * SATT + c0];
            #pragma unroll
            for (int i = 0; i < 4; i++)
                #pragma unroll
                for (int j = 0; j < 4; j++)
                    sacc[i][j] += a[i] * bb[j];
        }
        // epilogue: add gated position bias, mask invalid, store transposed
        #pragma unroll
        for (int j = 0; j < 4; j++) {
            int sg = s0 + c0 + j;
            #pragma unroll
            for (int i = 0; i < 4; i++) {
                float val;
                if (sg < SLEN) {
                    int tg = t0 + r0 + i;
                    val = sacc[i][j] +
                          gate_r[i] * g_pb[hx * 2048 + (sg - tg + 1023)];
                } else {
                    val = -1e30f;
                }
                Ss[(c0 + j) * SATT + (r0 + i)] = val;
            }
        }
        __syncthreads();

        // online softmax: partial max
        {
            int r = tid & 63, part = tid >> 6;
            float pm = -1e30f;
            #pragma unroll
            for (int i = 0; i < 16; i++)
                pm = fmaxf(pm, Ss[(part * 16 + i) * SATT + r]);
            red[part * 64 + r] = pm;
        }
        __syncthreads();
        if (tid < 64) {
            int r = tid;
            float mo = m_s[r];
            float cm = fmaxf(fmaxf(red[r], red[64 + r]),
                             fmaxf(red[128 + r], red[192 + r]));
            float mn = fmaxf(mo, cm);
            al_s[r] = __expf(mo - mn);
            m_s[r] = mn;
        }
        __syncthreads();
        // exponentiate + partial sums
        {
            int r = tid & 63, part = tid >> 6;
            float mn = m_s[r];
            float ps = 0.f;
            #pragma unroll
            for (int i = 0; i < 16; i++) {
                float p = __expf(Ss[(part * 16 + i) * SATT + r] - mn);
                Ss[(part * 16 + i) * SATT + r] = p;
                ps += p;
            }
            red[part * 64 + r] = ps;
        }
        __syncthreads();
        if (tid < 64) {
            int r = tid;
            l_s[r] = l_s[r] * al_s[r] +
                     red[r] + red[64 + r] + red[128 + r] + red[192 + r];
        }
        __syncthreads();

        // rescale accumulators + O += P @ V
        #pragma unroll
        for (int i = 0; i < 4; i++) {
            float a = al_s[r0 + i];
            #pragma unroll
            for (int j = 0; j < 4; j++) o[i][j] *= a;
        }
        #pragma unroll
        for (int k = 0; k < 64; k++) {
            float p[4], vv[4];
            *(float4*)p  = *(float4*)&Ss[k * SATT + r0];
            *(float4*)vv = *(float4*)&Vs[k * SATT + c0];
            #pragma unroll
            for (int i = 0; i < 4; i++)
                #pragma unroll
                for (int j = 0; j < 4; j++)
                    o[i][j] += p[i] * vv[j];
        }
        __syncthreads();
    }

    // normalize and scatter: out row = y*4 + bx, col = hx*64 + d
    #pragma unroll
    for (int i = 0; i < 4; i++) {
        int y = t0 + r0 + i;
        float inv = 1.0f / l_s[r0 + i];
        #pragma unroll
        for (int j = 0; j < 4; j++) {
            g_attn[((size_t)(y * BZ + bx)) * E_ + hx * HD + c0 + j] =
                o[i][j] * inv;
        }
    }
}

// ---------------- launch -----------------------------------------------
extern "C" void kernel_launch(void* const* d_in, const int* in_sizes, int n_in,
                              void* d_out, int out_size)
{
    (void)in_sizes; (void)n_in; (void)out_size;
    const float* query  = (const float*)d_in[0];
    const float* q_w    = (const float*)d_in[1];
    const float* q_b    = (const float*)d_in[2];
    const float* k_w    = (const float*)d_in[3];
    const float* k_b    = (const float*)d_in[4];
    const float* v_w    = (const float*)d_in[5];
    const float* v_b    = (const float*)d_in[6];
    const float* out_w  = (const float*)d_in[7];
    const float* out_b  = (const float*)d_in[8];
    const float* rel_emb = (const float*)d_in[9];
    const float* grep_w = (const float*)d_in[10];
    const float* grep_b = (const float*)d_in[11];
    const float* grep_a = (const float*)d_in[12];
    const float* bias_k = (const float*)d_in[13];
    const float* bias_v = (const float*)d_in[14];
    float* out = (float*)d_out;

    dim3 gemm_grid(8, 32);   // N/128 x M/128

    sgemm_kernel<0><<<gemm_grid, 256>>>(query, q_w, q_b, nullptr);
    sgemm_kernel<1><<<gemm_grid, 256>>>(query, k_w, k_b, nullptr);
    sgemm_kernel<2><<<gemm_grid, 256>>>(query, v_w, v_b, nullptr);
    biaskv_kernel<<<16, 256>>>(bias_k, bias_v);
    pb_kernel<<<8, 256>>>(rel_emb);
    gate_kernel<<<8192, 256>>>(grep_w, grep_b, grep_a);

    int attn_smem = (4 * 64 * SATT + 256 + 4 * 64) * (int)sizeof(float);
    cudaFuncSetAttribute((const void*)attn_kernel,
                         cudaFuncAttributeMaxDynamicSharedMemorySize,
                         attn_smem);
    attn_kernel<<<dim3(16, 64), 256, attn_smem>>>();

    sgemm_kernel<3><<<gemm_grid, 256>>>(nullptr, out_w, out_b, out);
}